// round 12
// baseline (speedup 1.0000x reference)
#include <cuda_runtime.h>
#include <cuda_bf16.h>
#include <cstdint>
#include <cstddef>

#define NN 100000
#define NE 1600000
#define IN_CH 128
#define OUT_CH 64
#define HEADS 2
#define EDGE_DIM 32
#define HC 128  // HEADS*OUT_CH

// ---------------- scratch (device globals; no allocation allowed) ----------------
__device__ float    g_wscale;                       // fake-quant scale for w_lin
__device__ __align__(16) unsigned short g_wqbf[HC * IN_CH];  // int-valued q as bf16, [n][k] row-major
__device__ float    g_vedge[HEADS * EDGE_DIM];      // att_edge @ w_edge  [h][j]
__device__ float    g_xp[(size_t)NN * HC];          // projected nodes [n][128]
__device__ float2   g_asrc[NN];
__device__ float2   g_adst[NN];
__device__ unsigned g_qmax;                         // raw bits of nonneg max |out|
__device__ int      g_is64 = 1;                     // edge_index dtype flag (1 = int64); detect only clears
// CSR-by-dst build
__device__ int      g_cnt[NN];
__device__ int      g_scan[NN];
__device__ int      g_bsum[256];
__device__ int      g_boff[256];
__device__ int      g_rowstart[NN + 1];
__device__ int      g_cursor[NN];
__device__ int      g_csr_src[NE];
__device__ float    g_csr_e0[NE];                   // exp(alpha) head 0
__device__ float    g_csr_e1[NE];                   // exp(alpha) head 1

__device__ __forceinline__ uint32_t smem_u32(const void* p) {
    uint32_t a;
    asm("{ .reg .u64 t; cvta.to.shared.u64 t, %1; cvt.u32.u64 %0, t; }" : "=r"(a) : "l"(p));
    return a;
}

// dtype-agnostic edge-index read (g_is64 decided by k_initdetect)
__device__ __forceinline__ int eidx(const void* ei, long long i) {
    if (g_is64) return (int)((const long long*)ei)[i];
    return ((const int*)ei)[i];
}

// ---------------- K_initdetect: zero counts/qmax + dtype detect ----------------
// int64 little-endian: odd 32-bit words of first 64K pairs all zero. g_is64 is
// statically 1; int32 data clears it (racy same-value stores: fine, deterministic).
__global__ void k_initdetect(const unsigned* __restrict__ ei_words) {
    int i = blockIdx.x * 256 + threadIdx.x;
    if (i < NN) g_cnt[i] = 0;
    if (i == 0) g_qmax = 0u;
    if (i < 65536 && ei_words[2 * i + 1] != 0u) g_is64 = 0;
}

// ---------------- K_prep: fake-quant w_lin -> bf16 int image [n][k] + v_edge -----
__global__ void k_prep(const float* __restrict__ wlin, const float* __restrict__ wedge,
                       const float* __restrict__ att_edge) {
    __shared__ float red[1024];
    int t = threadIdx.x;
    float m = 0.f;
    for (int i = t; i < HC * IN_CH; i += 1024) m = fmaxf(m, fabsf(wlin[i]));
    red[t] = m;
    __syncthreads();
    for (int s = 512; s > 0; s >>= 1) {
        if (t < s) red[t] = fmaxf(red[t], red[t + s]);
        __syncthreads();
    }
    float scale = red[0] / 127.f + 1e-12f;
    for (int i = t; i < HC * IN_CH; i += 1024) {
        float q = fminf(fmaxf(rintf(__fdiv_rn(wlin[i], scale)), -128.f), 127.f);
        // small ints have zero low 16 f32 bits -> exact bf16 via truncation
        g_wqbf[i] = (unsigned short)(__float_as_uint(q) >> 16);  // wlin is [n][k] row-major
    }
    if (t == 0) g_wscale = scale;
    if (t < HEADS * EDGE_DIM) {
        int h = t >> 5, j = t & 31;
        float s = 0.f;
        for (int c = 0; c < OUT_CH; c++)
            s += att_edge[h * OUT_CH + c] * wedge[(h * OUT_CH + c) * EDGE_DIM + j];
        g_vedge[t] = s;
    }
}

// ---------------- K_count: dst-degree histogram ----------------
__global__ void k_count(const void* __restrict__ ei) {
    int e = blockIdx.x * 256 + threadIdx.x;
    if (e < NE) atomicAdd(&g_cnt[eidx(ei, (long long)NE + e)], 1);
}

// ---------------- K_gemm: bf16-split mma.sync HMMA, fused logits epilogue --------
// smem rows padded to 272B (136 bf16): conflict-free ldmatrix (272 % 128 == 16)
#define ROWB 272
#define SM_ATTS 0
#define SM_ATTD 512
#define SM_A    1024
#define SM_ALO  (SM_A + 128 * ROWB)    // 35840
#define SM_B    (SM_ALO + 128 * ROWB)  // 70656
#define SM_TOT  (SM_B + 128 * ROWB)    // 105472

__device__ __forceinline__ void ldsm_x4(uint32_t* r, uint32_t addr) {
    asm volatile("ldmatrix.sync.aligned.m8n8.x4.shared.b16 {%0,%1,%2,%3}, [%4];"
                 : "=r"(r[0]), "=r"(r[1]), "=r"(r[2]), "=r"(r[3]) : "r"(addr));
}
__device__ __forceinline__ void ldsm_x2(uint32_t* r, uint32_t addr) {
    asm volatile("ldmatrix.sync.aligned.m8n8.x2.shared.b16 {%0,%1}, [%2];"
                 : "=r"(r[0]), "=r"(r[1]) : "r"(addr));
}
__device__ __forceinline__ void mma_bf16(float* c, const uint32_t* a, uint32_t b0, uint32_t b1) {
    asm volatile("mma.sync.aligned.m16n8k16.row.col.f32.bf16.bf16.f32 "
                 "{%0,%1,%2,%3}, {%4,%5,%6,%7}, {%8,%9}, {%0,%1,%2,%3};"
                 : "+f"(c[0]), "+f"(c[1]), "+f"(c[2]), "+f"(c[3])
                 : "r"(a[0]), "r"(a[1]), "r"(a[2]), "r"(a[3]), "r"(b0), "r"(b1));
}

__global__ void __launch_bounds__(256, 2) k_gemm(const float* __restrict__ x,
                                                 const float* __restrict__ att_src,
                                                 const float* __restrict__ att_dst) {
    extern __shared__ char smem[];
    uint32_t sbase = smem_u32(smem);
    int t = threadIdx.x;
    int wid = t >> 5, lane = t & 31;
    int m0 = blockIdx.x * 128;

    // att vectors
    if (t < 128) {
        ((float*)(smem + SM_ATTS))[t] = att_src[t];
        ((float*)(smem + SM_ATTD))[t] = att_dst[t];
    }
    // B: copy weight image [n][k] bf16 into padded rows
    for (int i = t; i < 128 * 32; i += 256) {
        int r = i >> 5, c4 = i & 31;
        *(uint2*)(smem + SM_B + r * ROWB + c4 * 8) = ((const uint2*)g_wqbf)[r * 32 + c4];
    }
    // A: load x tile, split into bf16 hi/lo, padded rows
    for (int i = t; i < 128 * 32; i += 256) {
        int r = i >> 5, c4 = i & 31;
        float4 v = make_float4(0.f, 0.f, 0.f, 0.f);
        if (m0 + r < NN) v = ((const float4*)(x + (size_t)(m0 + r) * IN_CH))[c4];
        uint32_t h01, h23;
        asm("cvt.rn.satfinite.bf16x2.f32 %0, %1, %2;" : "=r"(h01) : "f"(v.y), "f"(v.x));
        asm("cvt.rn.satfinite.bf16x2.f32 %0, %1, %2;" : "=r"(h23) : "f"(v.w), "f"(v.z));
        float l0 = v.x - __uint_as_float(h01 << 16);
        float l1 = v.y - __uint_as_float(h01 & 0xFFFF0000u);
        float l2 = v.z - __uint_as_float(h23 << 16);
        float l3 = v.w - __uint_as_float(h23 & 0xFFFF0000u);
        uint32_t L01, L23;
        asm("cvt.rn.satfinite.bf16x2.f32 %0, %1, %2;" : "=r"(L01) : "f"(l1), "f"(l0));
        asm("cvt.rn.satfinite.bf16x2.f32 %0, %1, %2;" : "=r"(L23) : "f"(l3), "f"(l2));
        *(uint2*)(smem + SM_A + r * ROWB + c4 * 8) = make_uint2(h01, h23);
        *(uint2*)(smem + SM_ALO + r * ROWB + c4 * 8) = make_uint2(L01, L23);
    }
    __syncthreads();

    // warp tiling: 4(m) x 2(n); warp tile 32m x 64n
    int wm = wid & 3, wn = wid >> 2;
    int g = lane & 7, sel = lane >> 3;  // ldmatrix address roles

    float acc[2][8][4];
#pragma unroll
    for (int mt = 0; mt < 2; mt++)
#pragma unroll
        for (int nt = 0; nt < 8; nt++)
#pragma unroll
            for (int c = 0; c < 4; c++) acc[mt][nt][c] = 0.f;

    // x4 A: lane -> matrix sel (0..3): row += (sel&1)*8, chunk += sel>>1
    uint32_t a_row = (uint32_t)(wm * 32 + ((sel & 1) << 3) + g);
    uint32_t a_co = (uint32_t)(sel >> 1);
    // x2 B: lanes 0..15 -> matrix (lane>>3): row n = g, chunk += matrix
    uint32_t b_co = (uint32_t)(sel & 1);

#pragma unroll
    for (int kk = 0; kk < 8; kk++) {
        uint32_t kc = (uint32_t)(kk * 2);
        uint32_t ah[2][4], al[2][4];
#pragma unroll
        for (int mt = 0; mt < 2; mt++) {
            uint32_t ro = (a_row + mt * 16) * ROWB + (kc + a_co) * 16;
            ldsm_x4(ah[mt], sbase + SM_A + ro);
            ldsm_x4(al[mt], sbase + SM_ALO + ro);
        }
#pragma unroll
        for (int nt = 0; nt < 8; nt++) {
            uint32_t baddr = sbase + SM_B + (uint32_t)(wn * 64 + nt * 8 + g) * ROWB + (kc + b_co) * 16;
            uint32_t b[2];
            ldsm_x2(b, baddr);
            mma_bf16(acc[0][nt], ah[0], b[0], b[1]);
            mma_bf16(acc[0][nt], al[0], b[0], b[1]);
            mma_bf16(acc[1][nt], ah[1], b[0], b[1]);
            mma_bf16(acc[1][nt], al[1], b[0], b[1]);
        }
    }

    // epilogue: scale, store xp, fused per-head logits (quad = one row)
    {
        float scale = g_wscale;
        int q = lane >> 2, qq = lane & 3;
        const float* aS = (const float*)(smem + SM_ATTS);
        const float* aD = (const float*)(smem + SM_ATTD);
#pragma unroll
        for (int mt = 0; mt < 2; mt++) {
#pragma unroll
            for (int rg = 0; rg < 2; rg++) {
                int m = m0 + wm * 32 + mt * 16 + rg * 8 + q;
                float s = 0.f, d = 0.f;
                if (m < NN) {
                    float* orow = g_xp + (size_t)m * HC;
#pragma unroll
                    for (int nt = 0; nt < 8; nt++) {
                        int col = wn * 64 + nt * 8 + qq * 2;
                        float v0 = acc[mt][nt][rg * 2 + 0] * scale;
                        float v1 = acc[mt][nt][rg * 2 + 1] * scale;
                        *(float2*)(orow + col) = make_float2(v0, v1);
                        s += v0 * aS[col] + v1 * aS[col + 1];
                        d += v0 * aD[col] + v1 * aD[col + 1];
                    }
                }
                s += __shfl_xor_sync(0xFFFFFFFFu, s, 1);
                s += __shfl_xor_sync(0xFFFFFFFFu, s, 2);
                d += __shfl_xor_sync(0xFFFFFFFFu, d, 1);
                d += __shfl_xor_sync(0xFFFFFFFFu, d, 2);
                if (qq == 0 && m < NN) {
                    (&g_asrc[m].x)[wn] = s;
                    (&g_adst[m].x)[wn] = d;
                }
            }
        }
    }
}

// ---------------- K_scan 1/2/3: exclusive scan of g_cnt -> rowstart, cursor -------
#define SCB 512
__global__ void k_scan1() {
    __shared__ int sm[SCB];
    int i = blockIdx.x * SCB + threadIdx.x;
    int v = (i < NN) ? g_cnt[i] : 0;
    sm[threadIdx.x] = v;
    __syncthreads();
    for (int off = 1; off < SCB; off <<= 1) {
        int add = (threadIdx.x >= off) ? sm[threadIdx.x - off] : 0;
        __syncthreads();
        sm[threadIdx.x] += add;
        __syncthreads();
    }
    if (i < NN) g_scan[i] = sm[threadIdx.x];
    if (threadIdx.x == SCB - 1) g_bsum[blockIdx.x] = sm[SCB - 1];
}
__global__ void k_scan2(int nblk) {
    __shared__ int sm[256];
    int t = threadIdx.x;
    int v = (t < nblk) ? g_bsum[t] : 0;
    sm[t] = v;
    __syncthreads();
    for (int off = 1; off < 256; off <<= 1) {
        int add = (t >= off) ? sm[t - off] : 0;
        __syncthreads();
        sm[t] += add;
        __syncthreads();
    }
    if (t < nblk) g_boff[t] = sm[t] - v;  // exclusive
}
__global__ void k_scan3() {
    int i = blockIdx.x * 256 + threadIdx.x;
    if (i < NN) {
        int ex = g_scan[i] - g_cnt[i] + g_boff[i >> 9];
        g_rowstart[i] = ex;
        g_cursor[i] = ex;
    } else if (i == NN) {
        g_rowstart[NN] = NE;
    }
}

// ---------------- K_edgeA: exp(alpha) + direct CSR write (8 lanes / edge) ---------
// no segment-max shift: alpha is O(+-10), exp() safely in fp32 range, and the
// softmax ratio exp(a)/sum(exp(a)) is mathematically identical with/without shift
__global__ void k_edgeA(const void* __restrict__ ei, const float* __restrict__ eattr) {
    int tid = blockIdx.x * 256 + threadIdx.x;
    int e = tid >> 3;
    int k4 = tid & 7;
    if (e >= NE) return;
    float4 v = ((const float4*)eattr)[(size_t)e * 8 + k4];
    const float* v0 = g_vedge + k4 * 4;
    const float* v1 = g_vedge + 32 + k4 * 4;
    float a0 = v.x * v0[0] + v.y * v0[1] + v.z * v0[2] + v.w * v0[3];
    float a1 = v.x * v1[0] + v.y * v1[1] + v.z * v1[2] + v.w * v1[3];
#pragma unroll
    for (int o = 4; o; o >>= 1) {
        a0 += __shfl_down_sync(0xFFFFFFFFu, a0, o);
        a1 += __shfl_down_sync(0xFFFFFFFFu, a1, o);
    }
    if (k4 == 0) {
        int s = eidx(ei, e);
        int d = eidx(ei, (long long)NE + e);
        float2 as = g_asrc[s];
        float2 ad = g_adst[d];
        float x0 = as.x + ad.x + a0;
        float x1 = as.y + ad.y + a1;
        x0 = x0 > 0.f ? x0 : 0.2f * x0;
        x1 = x1 > 0.f ? x1 : 0.2f * x1;
        int p = atomicAdd(&g_cursor[d], 1);
        g_csr_src[p] = s;
        g_csr_e0[p] = expf(x0);
        g_csr_e1[p] = expf(x1);
    }
}

// ---------------- K_aggregate v4: two warps per node (one per head) ---------------
// block = 256 thr = 4 node-pairs. Each head-warp gathers its 64 channels
// (2 LDG + 2 FMA + 2 SHFL per edge) -> 2x latency hiding at equal traffic.
// head1 deposits partials in smem; head0 combines, stores, feeds fused absmax.
__global__ void k_aggregate(float* __restrict__ out, const float* __restrict__ bias) {
    __shared__ float smA[4][64];
    __shared__ float smD[4];
    int gw = (blockIdx.x * 256 + threadIdx.x) >> 5;
    int lane = threadIdx.x & 31;
    int wid = threadIdx.x >> 5;
    int pair = wid >> 1, head = wid & 1;
    int w = gw >> 1;
    int start = 0, end = 0;
    if (w < NN) { start = g_rowstart[w]; end = g_rowstart[w + 1]; }
    const float* ce = head ? g_csr_e1 : g_csr_e0;
    const float* xb = g_xp + head * 64;

    float a0 = 0.f, a1 = 0.f, d = 0.f;
    for (int chunk = start; chunk < end; chunk += 32) {
        int j = chunk + lane;
        float e = 0.f;
        int sj = 0;
        if (j < end) { e = ce[j]; sj = g_csr_src[j]; }
        d += e;
        int cnt = min(32, end - chunk);
#pragma unroll 2
        for (int i = 0; i < cnt; i++) {
            float c = __shfl_sync(0xFFFFFFFFu, e, i);
            int s = __shfl_sync(0xFFFFFFFFu, sj, i);
            const float* xr = xb + (size_t)s * HC;
            a0 = fmaf(c, xr[lane], a0);
            a1 = fmaf(c, xr[lane + 32], a1);
        }
    }
#pragma unroll
    for (int o = 16; o; o >>= 1) d += __shfl_xor_sync(0xFFFFFFFFu, d, o);

    if (head) {
        smA[pair][lane] = a0;
        smA[pair][lane + 32] = a1;
        if (lane == 0) smD[pair] = d;
    }
    __syncthreads();
    if (!head && w < NN) {
        float i0 = 0.5f / (d + 1e-16f);
        float i1 = 0.5f / (smD[pair] + 1e-16f);
        float o0 = a0 * i0 + smA[pair][lane] * i1 + bias[lane];
        float o1 = a1 * i0 + smA[pair][lane + 32] * i1 + bias[lane + 32];
        out[(size_t)w * OUT_CH + lane] = o0;
        out[(size_t)w * OUT_CH + 32 + lane] = o1;
        float mm = fmaxf(fabsf(o0), fabsf(o1));
#pragma unroll
        for (int o = 16; o; o >>= 1) mm = fmaxf(mm, __shfl_xor_sync(0xFFFFFFFFu, mm, o));
        if (lane == 0) atomicMax(&g_qmax, __float_as_uint(mm));
    }
}

// ---------------- K_quant: output fake-quant, float4 (bias already applied) -------
__global__ void k_quant(float* __restrict__ out) {
    size_t i = (size_t)blockIdx.x * 256 + threadIdx.x;
    if (i >= (size_t)NN * OUT_CH / 4) return;
    float scale = __uint_as_float(g_qmax) / 127.f + 1e-12f;
    float4 v = ((float4*)out)[i];
    v.x = fminf(fmaxf(rintf(__fdiv_rn(v.x, scale)), -128.f), 127.f) * scale;
    v.y = fminf(fmaxf(rintf(__fdiv_rn(v.y, scale)), -128.f), 127.f) * scale;
    v.z = fminf(fmaxf(rintf(__fdiv_rn(v.z, scale)), -128.f), 127.f) * scale;
    v.w = fminf(fmaxf(rintf(__fdiv_rn(v.w, scale)), -128.f), 127.f) * scale;
    ((float4*)out)[i] = v;
}

// ---------------- launch ----------------
extern "C" void kernel_launch(void* const* d_in, const int* in_sizes, int n_in,
                              void* d_out, int out_size) {
    const float* x        = (const float*)d_in[0];
    const void*  ei       = d_in[1];
    const float* eattr    = (const float*)d_in[2];
    const float* wlin     = (const float*)d_in[3];
    const float* wedge    = (const float*)d_in[4];
    const float* att_src  = (const float*)d_in[5];
    const float* att_dst  = (const float*)d_in[6];
    const float* att_edge = (const float*)d_in[7];
    const float* bias     = (const float*)d_in[8];
    float* out = (float*)d_out;

    cudaFuncSetAttribute(k_gemm, cudaFuncAttributeMaxDynamicSharedMemorySize, SM_TOT);

    int nscanblk = (NN + SCB - 1) / SCB;  // 196

    k_initdetect<<<(NN + 255) / 256, 256>>>((const unsigned*)ei);
    k_prep<<<1, 1024>>>(wlin, wedge, att_edge);
    k_count<<<(NE + 255) / 256, 256>>>(ei);
    k_scan1<<<nscanblk, SCB>>>();
    k_scan2<<<1, 256>>>(nscanblk);
    k_scan3<<<(NN + 256) / 256, 256>>>();
    k_gemm<<<(NN + 127) / 128, 256, SM_TOT>>>(x, att_src, att_dst);
    k_edgeA<<<(NE * 8 + 255) / 256, 256>>>(ei, eattr);
    k_aggregate<<<(NN * 2 * 32 + 255) / 256, 256>>>(out, bias);
    k_quant<<<(NN * OUT_CH / 4 + 255) / 256, 256>>>(out);
}

// round 13
// speedup vs baseline: 1.1070x; 1.1070x over previous
#include <cuda_runtime.h>
#include <cuda_bf16.h>
#include <cstdint>
#include <cstddef>

#define NN 100000
#define NE 1600000
#define IN_CH 128
#define OUT_CH 64
#define HEADS 2
#define EDGE_DIM 32
#define HC 128  // HEADS*OUT_CH

// ---------------- scratch (device globals; no allocation allowed) ----------------
__device__ float    g_wscale;                       // fake-quant scale for w_lin
__device__ __align__(16) unsigned short g_wqbf[HC * IN_CH];  // int-valued q as bf16, [n][k] row-major
__device__ float    g_vedge[HEADS * EDGE_DIM];      // att_edge @ w_edge  [h][j]
__device__ float    g_xp[(size_t)NN * HC];          // projected nodes [n][128]
__device__ float2   g_asrc[NN];
__device__ float2   g_adst[NN];
__device__ unsigned g_qmax;                         // raw bits of nonneg max |out|
__device__ int      g_is64 = 1;                     // edge_index dtype flag; detect only clears
// CSR-by-dst build
__device__ int      g_cnt[NN];
__device__ int      g_scan[NN];
__device__ int      g_bsum[256];
__device__ int      g_boff[256];
__device__ int      g_rowstart[NN + 1];
__device__ int      g_cursor[NN];
__device__ int      g_csr_src[NE];
__device__ float2   g_csr_al[NE];                   // exp(alpha) per edge (no max shift needed)

__device__ __forceinline__ uint32_t smem_u32(const void* p) {
    uint32_t a;
    asm("{ .reg .u64 t; cvta.to.shared.u64 t, %1; cvt.u32.u64 %0, t; }" : "=r"(a) : "l"(p));
    return a;
}

// dtype-agnostic edge-index read (g_is64 decided by k_initdetect)
__device__ __forceinline__ int eidx(const void* ei, long long i) {
    if (g_is64) return (int)((const long long*)ei)[i];
    return ((const int*)ei)[i];
}

// ---------------- K_initdetect: zero counts/qmax + dtype detect ----------------
__global__ void k_initdetect(const unsigned* __restrict__ ei_words) {
    int i = blockIdx.x * 256 + threadIdx.x;
    if (i < NN) g_cnt[i] = 0;
    if (i == 0) g_qmax = 0u;
    if (i < 65536 && ei_words[2 * i + 1] != 0u) g_is64 = 0;  // racy same-value store: fine
}

// ---------------- K_prep: fake-quant w_lin -> bf16 int image [n][k] + v_edge -----
__global__ void k_prep(const float* __restrict__ wlin, const float* __restrict__ wedge,
                       const float* __restrict__ att_edge) {
    __shared__ float red[1024];
    int t = threadIdx.x;
    float m = 0.f;
    for (int i = t; i < HC * IN_CH; i += 1024) m = fmaxf(m, fabsf(wlin[i]));
    red[t] = m;
    __syncthreads();
    for (int s = 512; s > 0; s >>= 1) {
        if (t < s) red[t] = fmaxf(red[t], red[t + s]);
        __syncthreads();
    }
    float scale = red[0] / 127.f + 1e-12f;
    for (int i = t; i < HC * IN_CH; i += 1024) {
        float q = fminf(fmaxf(rintf(__fdiv_rn(wlin[i], scale)), -128.f), 127.f);
        // small ints have zero low 16 f32 bits -> exact bf16 via truncation
        g_wqbf[i] = (unsigned short)(__float_as_uint(q) >> 16);  // wlin is [n][k] row-major
    }
    if (t == 0) g_wscale = scale;
    if (t < HEADS * EDGE_DIM) {
        int h = t >> 5, j = t & 31;
        float s = 0.f;
        for (int c = 0; c < OUT_CH; c++)
            s += att_edge[h * OUT_CH + c] * wedge[(h * OUT_CH + c) * EDGE_DIM + j];
        g_vedge[t] = s;
    }
}

// ---------------- K_count: dst-degree histogram ----------------
__global__ void k_count(const void* __restrict__ ei) {
    int e = blockIdx.x * 256 + threadIdx.x;
    if (e < NE) atomicAdd(&g_cnt[eidx(ei, (long long)NE + e)], 1);
}

// ---------------- K_gemm: bf16-split mma.sync HMMA, fused logits epilogue --------
// smem rows padded to 272B (136 bf16): conflict-free ldmatrix (272 % 128 == 16)
#define ROWB 272
#define SM_ATTS 0
#define SM_ATTD 512
#define SM_A    1024
#define SM_ALO  (SM_A + 128 * ROWB)    // 35840
#define SM_B    (SM_ALO + 128 * ROWB)  // 70656
#define SM_TOT  (SM_B + 128 * ROWB)    // 105472

__device__ __forceinline__ void ldsm_x4(uint32_t* r, uint32_t addr) {
    asm volatile("ldmatrix.sync.aligned.m8n8.x4.shared.b16 {%0,%1,%2,%3}, [%4];"
                 : "=r"(r[0]), "=r"(r[1]), "=r"(r[2]), "=r"(r[3]) : "r"(addr));
}
__device__ __forceinline__ void ldsm_x2(uint32_t* r, uint32_t addr) {
    asm volatile("ldmatrix.sync.aligned.m8n8.x2.shared.b16 {%0,%1}, [%2];"
                 : "=r"(r[0]), "=r"(r[1]) : "r"(addr));
}
__device__ __forceinline__ void mma_bf16(float* c, const uint32_t* a, uint32_t b0, uint32_t b1) {
    asm volatile("mma.sync.aligned.m16n8k16.row.col.f32.bf16.bf16.f32 "
                 "{%0,%1,%2,%3}, {%4,%5,%6,%7}, {%8,%9}, {%0,%1,%2,%3};"
                 : "+f"(c[0]), "+f"(c[1]), "+f"(c[2]), "+f"(c[3])
                 : "r"(a[0]), "r"(a[1]), "r"(a[2]), "r"(a[3]), "r"(b0), "r"(b1));
}

__global__ void __launch_bounds__(256, 2) k_gemm(const float* __restrict__ x,
                                                 const float* __restrict__ att_src,
                                                 const float* __restrict__ att_dst) {
    extern __shared__ char smem[];
    uint32_t sbase = smem_u32(smem);
    int t = threadIdx.x;
    int wid = t >> 5, lane = t & 31;
    int m0 = blockIdx.x * 128;

    // att vectors
    if (t < 128) {
        ((float*)(smem + SM_ATTS))[t] = att_src[t];
        ((float*)(smem + SM_ATTD))[t] = att_dst[t];
    }
    // B: copy weight image [n][k] bf16 into padded rows
    for (int i = t; i < 128 * 32; i += 256) {
        int r = i >> 5, c4 = i & 31;
        *(uint2*)(smem + SM_B + r * ROWB + c4 * 8) = ((const uint2*)g_wqbf)[r * 32 + c4];
    }
    // A: load x tile, split into bf16 hi/lo, padded rows
    for (int i = t; i < 128 * 32; i += 256) {
        int r = i >> 5, c4 = i & 31;
        float4 v = make_float4(0.f, 0.f, 0.f, 0.f);
        if (m0 + r < NN) v = ((const float4*)(x + (size_t)(m0 + r) * IN_CH))[c4];
        uint32_t h01, h23;
        asm("cvt.rn.satfinite.bf16x2.f32 %0, %1, %2;" : "=r"(h01) : "f"(v.y), "f"(v.x));
        asm("cvt.rn.satfinite.bf16x2.f32 %0, %1, %2;" : "=r"(h23) : "f"(v.w), "f"(v.z));
        float l0 = v.x - __uint_as_float(h01 << 16);
        float l1 = v.y - __uint_as_float(h01 & 0xFFFF0000u);
        float l2 = v.z - __uint_as_float(h23 << 16);
        float l3 = v.w - __uint_as_float(h23 & 0xFFFF0000u);
        uint32_t L01, L23;
        asm("cvt.rn.satfinite.bf16x2.f32 %0, %1, %2;" : "=r"(L01) : "f"(l1), "f"(l0));
        asm("cvt.rn.satfinite.bf16x2.f32 %0, %1, %2;" : "=r"(L23) : "f"(l3), "f"(l2));
        *(uint2*)(smem + SM_A + r * ROWB + c4 * 8) = make_uint2(h01, h23);
        *(uint2*)(smem + SM_ALO + r * ROWB + c4 * 8) = make_uint2(L01, L23);
    }
    __syncthreads();

    // warp tiling: 4(m) x 2(n); warp tile 32m x 64n
    int wm = wid & 3, wn = wid >> 2;
    int g = lane & 7, sel = lane >> 3;  // ldmatrix address roles

    float acc[2][8][4];
#pragma unroll
    for (int mt = 0; mt < 2; mt++)
#pragma unroll
        for (int nt = 0; nt < 8; nt++)
#pragma unroll
            for (int c = 0; c < 4; c++) acc[mt][nt][c] = 0.f;

    // x4 A: lane -> matrix sel (0..3): row += (sel&1)*8, chunk += sel>>1
    uint32_t a_row = (uint32_t)(wm * 32 + ((sel & 1) << 3) + g);
    uint32_t a_co = (uint32_t)(sel >> 1);
    // x2 B: lanes 0..15 -> matrix (lane>>3): row n = g, chunk += matrix
    uint32_t b_co = (uint32_t)(sel & 1);

#pragma unroll
    for (int kk = 0; kk < 8; kk++) {
        uint32_t kc = (uint32_t)(kk * 2);
        uint32_t ah[2][4], al[2][4];
#pragma unroll
        for (int mt = 0; mt < 2; mt++) {
            uint32_t ro = (a_row + mt * 16) * ROWB + (kc + a_co) * 16;
            ldsm_x4(ah[mt], sbase + SM_A + ro);
            ldsm_x4(al[mt], sbase + SM_ALO + ro);
        }
#pragma unroll
        for (int nt = 0; nt < 8; nt++) {
            uint32_t baddr = sbase + SM_B + (uint32_t)(wn * 64 + nt * 8 + g) * ROWB + (kc + b_co) * 16;
            uint32_t b[2];
            ldsm_x2(b, baddr);
            mma_bf16(acc[0][nt], ah[0], b[0], b[1]);
            mma_bf16(acc[0][nt], al[0], b[0], b[1]);
            mma_bf16(acc[1][nt], ah[1], b[0], b[1]);
            mma_bf16(acc[1][nt], al[1], b[0], b[1]);
        }
    }

    // epilogue: scale, store xp, fused per-head logits (quad = one row)
    {
        float scale = g_wscale;
        int q = lane >> 2, qq = lane & 3;
        const float* aS = (const float*)(smem + SM_ATTS);
        const float* aD = (const float*)(smem + SM_ATTD);
#pragma unroll
        for (int mt = 0; mt < 2; mt++) {
#pragma unroll
            for (int rg = 0; rg < 2; rg++) {
                int m = m0 + wm * 32 + mt * 16 + rg * 8 + q;
                float s = 0.f, d = 0.f;
                if (m < NN) {
                    float* orow = g_xp + (size_t)m * HC;
#pragma unroll
                    for (int nt = 0; nt < 8; nt++) {
                        int col = wn * 64 + nt * 8 + qq * 2;
                        float v0 = acc[mt][nt][rg * 2 + 0] * scale;
                        float v1 = acc[mt][nt][rg * 2 + 1] * scale;
                        *(float2*)(orow + col) = make_float2(v0, v1);
                        s += v0 * aS[col] + v1 * aS[col + 1];
                        d += v0 * aD[col] + v1 * aD[col + 1];
                    }
                }
                s += __shfl_xor_sync(0xFFFFFFFFu, s, 1);
                s += __shfl_xor_sync(0xFFFFFFFFu, s, 2);
                d += __shfl_xor_sync(0xFFFFFFFFu, d, 1);
                d += __shfl_xor_sync(0xFFFFFFFFu, d, 2);
                if (qq == 0 && m < NN) {
                    (&g_asrc[m].x)[wn] = s;
                    (&g_adst[m].x)[wn] = d;
                }
            }
        }
    }
}

// ---------------- K_scan 1/2/3: exclusive scan of g_cnt -> rowstart, cursor -------
#define SCB 512
__global__ void k_scan1() {
    __shared__ int sm[SCB];
    int i = blockIdx.x * SCB + threadIdx.x;
    int v = (i < NN) ? g_cnt[i] : 0;
    sm[threadIdx.x] = v;
    __syncthreads();
    for (int off = 1; off < SCB; off <<= 1) {
        int add = (threadIdx.x >= off) ? sm[threadIdx.x - off] : 0;
        __syncthreads();
        sm[threadIdx.x] += add;
        __syncthreads();
    }
    if (i < NN) g_scan[i] = sm[threadIdx.x];
    if (threadIdx.x == SCB - 1) g_bsum[blockIdx.x] = sm[SCB - 1];
}
__global__ void k_scan2(int nblk) {
    __shared__ int sm[256];
    int t = threadIdx.x;
    int v = (t < nblk) ? g_bsum[t] : 0;
    sm[t] = v;
    __syncthreads();
    for (int off = 1; off < 256; off <<= 1) {
        int add = (t >= off) ? sm[t - off] : 0;
        __syncthreads();
        sm[t] += add;
        __syncthreads();
    }
    if (t < nblk) g_boff[t] = sm[t] - v;  // exclusive
}
__global__ void k_scan3() {
    int i = blockIdx.x * 256 + threadIdx.x;
    if (i < NN) {
        int ex = g_scan[i] - g_cnt[i] + g_boff[i >> 9];
        g_rowstart[i] = ex;
        g_cursor[i] = ex;
    } else if (i == NN) {
        g_rowstart[NN] = NE;
    }
}

// ---------------- K_edgeA: exp(alpha) + direct CSR write (8 lanes / edge) ---------
// no segment-max shift: alpha is O(+-10), exp() safely in fp32 range, and the
// softmax ratio exp(a)/sum(exp(a)) is mathematically identical with/without shift
__global__ void k_edgeA(const void* __restrict__ ei, const float* __restrict__ eattr) {
    int tid = blockIdx.x * 256 + threadIdx.x;
    int e = tid >> 3;
    int k4 = tid & 7;
    if (e >= NE) return;
    float4 v = ((const float4*)eattr)[(size_t)e * 8 + k4];
    const float* v0 = g_vedge + k4 * 4;
    const float* v1 = g_vedge + 32 + k4 * 4;
    float a0 = v.x * v0[0] + v.y * v0[1] + v.z * v0[2] + v.w * v0[3];
    float a1 = v.x * v1[0] + v.y * v1[1] + v.z * v1[2] + v.w * v1[3];
#pragma unroll
    for (int o = 4; o; o >>= 1) {
        a0 += __shfl_down_sync(0xFFFFFFFFu, a0, o);
        a1 += __shfl_down_sync(0xFFFFFFFFu, a1, o);
    }
    if (k4 == 0) {
        int s = eidx(ei, e);
        int d = eidx(ei, (long long)NE + e);
        float2 as = g_asrc[s];
        float2 ad = g_adst[d];
        float x0 = as.x + ad.x + a0;
        float x1 = as.y + ad.y + a1;
        x0 = x0 > 0.f ? x0 : 0.2f * x0;
        x1 = x1 > 0.f ? x1 : 0.2f * x1;
        int p = atomicAdd(&g_cursor[d], 1);
        g_csr_src[p] = s;
        g_csr_al[p] = make_float2(expf(x0), expf(x1));
    }
}

// ---------------- K_aggregate v3r: single-pass shuffle-broadcast pull -------------
// one warp per dst node; exp precomputed in csr_al; unroll 4 deepens the load
// pipeline across broadcast iterations.
__global__ void k_aggregate(float* __restrict__ out, const float* __restrict__ bias) {
    int w = (blockIdx.x * blockDim.x + threadIdx.x) >> 5;
    int lane = threadIdx.x & 31;
    if (w >= NN) return;
    int start = g_rowstart[w], end = g_rowstart[w + 1];

    float a0 = 0.f, a1 = 0.f, a2 = 0.f, a3 = 0.f, d0 = 0.f, d1 = 0.f;
    for (int chunk = start; chunk < end; chunk += 32) {
        int j = chunk + lane;
        float e0 = 0.f, e1 = 0.f;
        int sj = 0;
        if (j < end) {
            float2 al = g_csr_al[j];
            e0 = al.x;
            e1 = al.y;
            sj = g_csr_src[j];
        }
        d0 += e0;
        d1 += e1;
        int cnt = min(32, end - chunk);
#pragma unroll 4
        for (int i = 0; i < cnt; i++) {
            float c0 = __shfl_sync(0xFFFFFFFFu, e0, i);
            float c1 = __shfl_sync(0xFFFFFFFFu, e1, i);
            int s = __shfl_sync(0xFFFFFFFFu, sj, i);
            const float* xr = g_xp + (size_t)s * HC;
            a0 = fmaf(c0, xr[lane], a0);
            a1 = fmaf(c0, xr[lane + 32], a1);
            a2 = fmaf(c1, xr[lane + 64], a2);
            a3 = fmaf(c1, xr[lane + 96], a3);
        }
    }
#pragma unroll
    for (int o = 16; o; o >>= 1) {
        d0 += __shfl_xor_sync(0xFFFFFFFFu, d0, o);
        d1 += __shfl_xor_sync(0xFFFFFFFFu, d1, o);
    }

    float i0 = 0.5f / (d0 + 1e-16f);
    float i1 = 0.5f / (d1 + 1e-16f);
    float o0 = a0 * i0 + a2 * i1 + bias[lane];
    float o1 = a1 * i0 + a3 * i1 + bias[lane + 32];
    out[(size_t)w * OUT_CH + lane] = o0;
    out[(size_t)w * OUT_CH + 32 + lane] = o1;

    float mm = fmaxf(fabsf(o0), fabsf(o1));
#pragma unroll
    for (int o = 16; o; o >>= 1) mm = fmaxf(mm, __shfl_xor_sync(0xFFFFFFFFu, mm, o));
    if (lane == 0) atomicMax(&g_qmax, __float_as_uint(mm));
}

// ---------------- K_quant: output fake-quant, float4 (bias already applied) -------
__global__ void k_quant(float* __restrict__ out) {
    size_t i = (size_t)blockIdx.x * 256 + threadIdx.x;
    if (i >= (size_t)NN * OUT_CH / 4) return;
    float scale = __uint_as_float(g_qmax) / 127.f + 1e-12f;
    float4 v = ((float4*)out)[i];
    v.x = fminf(fmaxf(rintf(__fdiv_rn(v.x, scale)), -128.f), 127.f) * scale;
    v.y = fminf(fmaxf(rintf(__fdiv_rn(v.y, scale)), -128.f), 127.f) * scale;
    v.z = fminf(fmaxf(rintf(__fdiv_rn(v.z, scale)), -128.f), 127.f) * scale;
    v.w = fminf(fmaxf(rintf(__fdiv_rn(v.w, scale)), -128.f), 127.f) * scale;
    ((float4*)out)[i] = v;
}

// ---------------- launch ----------------
// NOTE: k_gemm moved to launch index 3 (depends only on initdetect+prep) so the
// ncu window (which captures the 4th launch) profiles the GEMM next round.
extern "C" void kernel_launch(void* const* d_in, const int* in_sizes, int n_in,
                              void* d_out, int out_size) {
    const float* x        = (const float*)d_in[0];
    const void*  ei       = d_in[1];
    const float* eattr    = (const float*)d_in[2];
    const float* wlin     = (const float*)d_in[3];
    const float* wedge    = (const float*)d_in[4];
    const float* att_src  = (const float*)d_in[5];
    const float* att_dst  = (const float*)d_in[6];
    const float* att_edge = (const float*)d_in[7];
    const float* bias     = (const float*)d_in[8];
    float* out = (float*)d_out;

    cudaFuncSetAttribute(k_gemm, cudaFuncAttributeMaxDynamicSharedMemorySize, SM_TOT);

    int nscanblk = (NN + SCB - 1) / SCB;  // 196

    k_initdetect<<<(NN + 255) / 256, 256>>>((const unsigned*)ei);
    k_prep<<<1, 1024>>>(wlin, wedge, att_edge);
    k_count<<<(NE + 255) / 256, 256>>>(ei);
    k_gemm<<<(NN + 127) / 128, 256, SM_TOT>>>(x, att_src, att_dst);
    k_scan1<<<nscanblk, SCB>>>();
    k_scan2<<<1, 256>>>(nscanblk);
    k_scan3<<<(NN + 256) / 256, 256>>>();
    k_edgeA<<<(NE * 8 + 255) / 256, 256>>>(ei, eattr);
    k_aggregate<<<(NN * 32 + 255) / 256, 256>>>(out, bias);
    k_quant<<<(NN * OUT_CH / 4 + 255) / 256, 256>>>(out);
}

// round 15
// speedup vs baseline: 1.1329x; 1.0234x over previous
#include <cuda_runtime.h>
#include <cuda_bf16.h>
#include <cstdint>
#include <cstddef>

#define NN 100000
#define NE 1600000
#define IN_CH 128
#define OUT_CH 64
#define HEADS 2
#define EDGE_DIM 32
#define HC 128  // HEADS*OUT_CH

// ---------------- scratch (device globals; no allocation allowed) ----------------
__device__ float    g_wscale;                       // fake-quant scale for w_lin
__device__ __align__(16) unsigned short g_wqbf[HC * IN_CH];  // int-valued q as bf16, [n][k] row-major
__device__ float    g_vedge[HEADS * EDGE_DIM];      // att_edge @ w_edge  [h][j]
__device__ float    g_xp[(size_t)NN * HC];          // projected nodes [n][128]
__device__ float2   g_asrc[NN];
__device__ float2   g_adst[NN];
__device__ unsigned g_qmax;                         // raw bits of nonneg max |out|
__device__ int      g_is64 = 1;                     // edge_index dtype flag; detect only clears
// CSR-by-dst build
__device__ int      g_cnt[NN];
__device__ int      g_scan[NN];
__device__ int      g_bsum[256];
__device__ int      g_boff[256];
__device__ int      g_rowstart[NN + 1];
__device__ int      g_cursor[NN];
__device__ int      g_csr_src[NE];
__device__ float2   g_csr_al[NE];                   // exp(alpha) per edge (no max shift needed)

__device__ __forceinline__ uint32_t smem_u32(const void* p) {
    uint32_t a;
    asm("{ .reg .u64 t; cvta.to.shared.u64 t, %1; cvt.u32.u64 %0, t; }" : "=r"(a) : "l"(p));
    return a;
}

// dtype-agnostic edge-index read (g_is64 decided by k_initdetect)
__device__ __forceinline__ int eidx(const void* ei, long long i) {
    if (g_is64) return (int)((const long long*)ei)[i];
    return ((const int*)ei)[i];
}

// ---------------- K_initdetect: zero counts/logits/qmax + dtype detect ------------
__global__ void k_initdetect(const unsigned* __restrict__ ei_words) {
    int i = blockIdx.x * 256 + threadIdx.x;
    if (i < NN) {
        g_cnt[i] = 0;
        g_asrc[i] = make_float2(0.f, 0.f);   // gemm epilogue accumulates via atomics
        g_adst[i] = make_float2(0.f, 0.f);
    }
    if (i == 0) g_qmax = 0u;
    if (i < 65536 && ei_words[2 * i + 1] != 0u) g_is64 = 0;  // racy same-value store: fine
}

// ---------------- K_prep: fake-quant w_lin -> bf16 int image [n][k] + v_edge -----
__global__ void k_prep(const float* __restrict__ wlin, const float* __restrict__ wedge,
                       const float* __restrict__ att_edge) {
    __shared__ float red[1024];
    int t = threadIdx.x;
    float m = 0.f;
    for (int i = t; i < HC * IN_CH; i += 1024) m = fmaxf(m, fabsf(wlin[i]));
    red[t] = m;
    __syncthreads();
    for (int s = 512; s > 0; s >>= 1) {
        if (t < s) red[t] = fmaxf(red[t], red[t + s]);
        __syncthreads();
    }
    float scale = red[0] / 127.f + 1e-12f;
    for (int i = t; i < HC * IN_CH; i += 1024) {
        float q = fminf(fmaxf(rintf(__fdiv_rn(wlin[i], scale)), -128.f), 127.f);
        // small ints have zero low 16 f32 bits -> exact bf16 via truncation
        g_wqbf[i] = (unsigned short)(__float_as_uint(q) >> 16);  // wlin is [n][k] row-major
    }
    if (t == 0) g_wscale = scale;
    if (t < HEADS * EDGE_DIM) {
        int h = t >> 5, j = t & 31;
        float s = 0.f;
        for (int c = 0; c < OUT_CH; c++)
            s += att_edge[h * OUT_CH + c] * wedge[(h * OUT_CH + c) * EDGE_DIM + j];
        g_vedge[t] = s;
    }
}

// ---------------- K_count: dst-degree histogram ----------------
__global__ void k_count(const void* __restrict__ ei) {
    int e = blockIdx.x * 256 + threadIdx.x;
    if (e < NE) atomicAdd(&g_cnt[eidx(ei, (long long)NE + e)], 1);
}

// ---------------- K_gemm v2: BM=64, 3 CTAs/SM, bf16-split HMMA -------------------
// smem rows padded to 272B (136 bf16): conflict-free ldmatrix (272 % 128 == 16)
#define BM 64
#define ROWB 272
#define SM_ATTS 0
#define SM_ATTD 512
#define SM_A    1024
#define SM_ALO  (SM_A + BM * ROWB)     // 18432
#define SM_B    (SM_ALO + BM * ROWB)   // 35840
#define SM_TOT  (SM_B + 128 * ROWB)    // 70656

__device__ __forceinline__ void ldsm_x4(uint32_t* r, uint32_t addr) {
    asm volatile("ldmatrix.sync.aligned.m8n8.x4.shared.b16 {%0,%1,%2,%3}, [%4];"
                 : "=r"(r[0]), "=r"(r[1]), "=r"(r[2]), "=r"(r[3]) : "r"(addr));
}
__device__ __forceinline__ void ldsm_x2(uint32_t* r, uint32_t addr) {
    asm volatile("ldmatrix.sync.aligned.m8n8.x2.shared.b16 {%0,%1}, [%2];"
                 : "=r"(r[0]), "=r"(r[1]) : "r"(addr));
}
__device__ __forceinline__ void mma_bf16(float* c, const uint32_t* a, uint32_t b0, uint32_t b1) {
    asm volatile("mma.sync.aligned.m16n8k16.row.col.f32.bf16.bf16.f32 "
                 "{%0,%1,%2,%3}, {%4,%5,%6,%7}, {%8,%9}, {%0,%1,%2,%3};"
                 : "+f"(c[0]), "+f"(c[1]), "+f"(c[2]), "+f"(c[3])
                 : "r"(a[0]), "r"(a[1]), "r"(a[2]), "r"(a[3]), "r"(b0), "r"(b1));
}

__global__ void __launch_bounds__(256, 3) k_gemm(const float* __restrict__ x,
                                                 const float* __restrict__ att_src,
                                                 const float* __restrict__ att_dst) {
    extern __shared__ char smem[];
    uint32_t sbase = smem_u32(smem);
    int t = threadIdx.x;
    int wid = t >> 5, lane = t & 31;
    int m0 = blockIdx.x * BM;

    // att vectors
    if (t < 128) {
        ((float*)(smem + SM_ATTS))[t] = att_src[t];
        ((float*)(smem + SM_ATTD))[t] = att_dst[t];
    }
    // B: copy weight image [n][k] bf16 into padded rows (128 rows)
    for (int i = t; i < 128 * 32; i += 256) {
        int r = i >> 5, c4 = i & 31;
        *(uint2*)(smem + SM_B + r * ROWB + c4 * 8) = ((const uint2*)g_wqbf)[r * 32 + c4];
    }
    // A: load x tile (64 rows), split into bf16 hi/lo, padded rows
    for (int i = t; i < BM * 32; i += 256) {
        int r = i >> 5, c4 = i & 31;
        float4 v = make_float4(0.f, 0.f, 0.f, 0.f);
        if (m0 + r < NN) v = ((const float4*)(x + (size_t)(m0 + r) * IN_CH))[c4];
        uint32_t h01, h23;
        asm("cvt.rn.satfinite.bf16x2.f32 %0, %1, %2;" : "=r"(h01) : "f"(v.y), "f"(v.x));
        asm("cvt.rn.satfinite.bf16x2.f32 %0, %1, %2;" : "=r"(h23) : "f"(v.w), "f"(v.z));
        float l0 = v.x - __uint_as_float(h01 << 16);
        float l1 = v.y - __uint_as_float(h01 & 0xFFFF0000u);
        float l2 = v.z - __uint_as_float(h23 << 16);
        float l3 = v.w - __uint_as_float(h23 & 0xFFFF0000u);
        uint32_t L01, L23;
        asm("cvt.rn.satfinite.bf16x2.f32 %0, %1, %2;" : "=r"(L01) : "f"(l1), "f"(l0));
        asm("cvt.rn.satfinite.bf16x2.f32 %0, %1, %2;" : "=r"(L23) : "f"(l3), "f"(l2));
        *(uint2*)(smem + SM_A + r * ROWB + c4 * 8) = make_uint2(h01, h23);
        *(uint2*)(smem + SM_ALO + r * ROWB + c4 * 8) = make_uint2(L01, L23);
    }
    __syncthreads();

    // warp tiling: 2(m) x 4(n); warp tile 32m x 32n
    int wm = wid & 1, wn = wid >> 1;
    int g = lane & 7, sel = lane >> 3;  // ldmatrix address roles

    float acc[2][4][4];
#pragma unroll
    for (int mt = 0; mt < 2; mt++)
#pragma unroll
        for (int nt = 0; nt < 4; nt++)
#pragma unroll
            for (int c = 0; c < 4; c++) acc[mt][nt][c] = 0.f;

    uint32_t a_row = (uint32_t)(wm * 32 + ((sel & 1) << 3) + g);
    uint32_t a_co = (uint32_t)(sel >> 1);
    uint32_t b_co = (uint32_t)(sel & 1);

#pragma unroll
    for (int kk = 0; kk < 8; kk++) {
        uint32_t kc = (uint32_t)(kk * 2);
        uint32_t ah[2][4], al[2][4];
#pragma unroll
        for (int mt = 0; mt < 2; mt++) {
            uint32_t ro = (a_row + mt * 16) * ROWB + (kc + a_co) * 16;
            ldsm_x4(ah[mt], sbase + SM_A + ro);
            ldsm_x4(al[mt], sbase + SM_ALO + ro);
        }
#pragma unroll
        for (int nt = 0; nt < 4; nt++) {
            uint32_t baddr = sbase + SM_B + (uint32_t)(wn * 32 + nt * 8 + g) * ROWB + (kc + b_co) * 16;
            uint32_t b[2];
            ldsm_x2(b, baddr);
            mma_bf16(acc[0][nt], ah[0], b[0], b[1]);
            mma_bf16(acc[0][nt], al[0], b[0], b[1]);
            mma_bf16(acc[1][nt], ah[1], b[0], b[1]);
            mma_bf16(acc[1][nt], al[1], b[0], b[1]);
        }
    }

    // epilogue: scale, store xp, partial logits (32 cols/warp) via quad reduce + atomics
    {
        float scale = g_wscale;
        int q = lane >> 2, qq = lane & 3;
        int head = wn >> 1;
        const float* aS = (const float*)(smem + SM_ATTS);
        const float* aD = (const float*)(smem + SM_ATTD);
#pragma unroll
        for (int mt = 0; mt < 2; mt++) {
#pragma unroll
            for (int rg = 0; rg < 2; rg++) {
                int m = m0 + wm * 32 + mt * 16 + rg * 8 + q;
                float s = 0.f, d = 0.f;
                if (m < NN) {
                    float* orow = g_xp + (size_t)m * HC;
#pragma unroll
                    for (int nt = 0; nt < 4; nt++) {
                        int col = wn * 32 + nt * 8 + qq * 2;
                        float v0 = acc[mt][nt][rg * 2 + 0] * scale;
                        float v1 = acc[mt][nt][rg * 2 + 1] * scale;
                        *(float2*)(orow + col) = make_float2(v0, v1);
                        s += v0 * aS[col] + v1 * aS[col + 1];
                        d += v0 * aD[col] + v1 * aD[col + 1];
                    }
                }
                s += __shfl_xor_sync(0xFFFFFFFFu, s, 1);
                s += __shfl_xor_sync(0xFFFFFFFFu, s, 2);
                d += __shfl_xor_sync(0xFFFFFFFFu, d, 1);
                d += __shfl_xor_sync(0xFFFFFFFFu, d, 2);
                if (qq == 0 && m < NN) {
                    atomicAdd(&(&g_asrc[m].x)[head], s);
                    atomicAdd(&(&g_adst[m].x)[head], d);
                }
            }
        }
    }
}

// ---------------- K_scan 1/2/3: exclusive scan of g_cnt -> rowstart, cursor -------
#define SCB 512
__global__ void k_scan1() {
    __shared__ int sm[SCB];
    int i = blockIdx.x * SCB + threadIdx.x;
    int v = (i < NN) ? g_cnt[i] : 0;
    sm[threadIdx.x] = v;
    __syncthreads();
    for (int off = 1; off < SCB; off <<= 1) {
        int add = (threadIdx.x >= off) ? sm[threadIdx.x - off] : 0;
        __syncthreads();
        sm[threadIdx.x] += add;
        __syncthreads();
    }
    if (i < NN) g_scan[i] = sm[threadIdx.x];
    if (threadIdx.x == SCB - 1) g_bsum[blockIdx.x] = sm[SCB - 1];
}
__global__ void k_scan2(int nblk) {
    __shared__ int sm[256];
    int t = threadIdx.x;
    int v = (t < nblk) ? g_bsum[t] : 0;
    sm[t] = v;
    __syncthreads();
    for (int off = 1; off < 256; off <<= 1) {
        int add = (t >= off) ? sm[t - off] : 0;
        __syncthreads();
        sm[t] += add;
        __syncthreads();
    }
    if (t < nblk) g_boff[t] = sm[t] - v;  // exclusive
}
__global__ void k_scan3() {
    int i = blockIdx.x * 256 + threadIdx.x;
    if (i < NN) {
        int ex = g_scan[i] - g_cnt[i] + g_boff[i >> 9];
        g_rowstart[i] = ex;
        g_cursor[i] = ex;
    } else if (i == NN) {
        g_rowstart[NN] = NE;
    }
}

// ---------------- K_edgeA: exp(alpha) + direct CSR write (8 lanes / edge) ---------
__global__ void k_edgeA(const void* __restrict__ ei, const float* __restrict__ eattr) {
    int tid = blockIdx.x * 256 + threadIdx.x;
    int e = tid >> 3;
    int k4 = tid & 7;
    if (e >= NE) return;
    float4 v = ((const float4*)eattr)[(size_t)e * 8 + k4];
    const float* v0 = g_vedge + k4 * 4;
    const float* v1 = g_vedge + 32 + k4 * 4;
    float a0 = v.x * v0[0] + v.y * v0[1] + v.z * v0[2] + v.w * v0[3];
    float a1 = v.x * v1[0] + v.y * v1[1] + v.z * v1[2] + v.w * v1[3];
#pragma unroll
    for (int o = 4; o; o >>= 1) {
        a0 += __shfl_down_sync(0xFFFFFFFFu, a0, o);
        a1 += __shfl_down_sync(0xFFFFFFFFu, a1, o);
    }
    if (k4 == 0) {
        int s = eidx(ei, e);
        int d = eidx(ei, (long long)NE + e);
        float2 as = g_asrc[s];
        float2 ad = g_adst[d];
        float x0 = as.x + ad.x + a0;
        float x1 = as.y + ad.y + a1;
        x0 = x0 > 0.f ? x0 : 0.2f * x0;
        x1 = x1 > 0.f ? x1 : 0.2f * x1;
        int p = atomicAdd(&g_cursor[d], 1);
        g_csr_src[p] = s;
        g_csr_al[p] = make_float2(expf(x0), expf(x1));
    }
}

// ---------------- K_aggregate v3: single-pass shuffle-broadcast pull --------------
__global__ void k_aggregate(float* __restrict__ out, const float* __restrict__ bias) {
    int w = (blockIdx.x * blockDim.x + threadIdx.x) >> 5;
    int lane = threadIdx.x & 31;
    if (w >= NN) return;
    int start = g_rowstart[w], end = g_rowstart[w + 1];

    float a0 = 0.f, a1 = 0.f, a2 = 0.f, a3 = 0.f, d0 = 0.f, d1 = 0.f;
    for (int chunk = start; chunk < end; chunk += 32) {
        int j = chunk + lane;
        float e0 = 0.f, e1 = 0.f;
        int sj = 0;
        if (j < end) {
            float2 al = g_csr_al[j];
            e0 = al.x;
            e1 = al.y;
            sj = g_csr_src[j];
        }
        d0 += e0;
        d1 += e1;
        int cnt = min(32, end - chunk);
#pragma unroll 2
        for (int i = 0; i < cnt; i++) {
            float c0 = __shfl_sync(0xFFFFFFFFu, e0, i);
            float c1 = __shfl_sync(0xFFFFFFFFu, e1, i);
            int s = __shfl_sync(0xFFFFFFFFu, sj, i);
            const float* xr = g_xp + (size_t)s * HC;
            a0 = fmaf(c0, xr[lane], a0);
            a1 = fmaf(c0, xr[lane + 32], a1);
            a2 = fmaf(c1, xr[lane + 64], a2);
            a3 = fmaf(c1, xr[lane + 96], a3);
        }
    }
#pragma unroll
    for (int o = 16; o; o >>= 1) {
        d0 += __shfl_xor_sync(0xFFFFFFFFu, d0, o);
        d1 += __shfl_xor_sync(0xFFFFFFFFu, d1, o);
    }

    float i0 = 0.5f / (d0 + 1e-16f);
    float i1 = 0.5f / (d1 + 1e-16f);
    float o0 = a0 * i0 + a2 * i1 + bias[lane];
    float o1 = a1 * i0 + a3 * i1 + bias[lane + 32];
    out[(size_t)w * OUT_CH + lane] = o0;
    out[(size_t)w * OUT_CH + 32 + lane] = o1;

    float mm = fmaxf(fabsf(o0), fabsf(o1));
#pragma unroll
    for (int o = 16; o; o >>= 1) mm = fmaxf(mm, __shfl_xor_sync(0xFFFFFFFFu, mm, o));
    if (lane == 0) atomicMax(&g_qmax, __float_as_uint(mm));
}

// ---------------- K_quant: output fake-quant, float4 (bias already applied) -------
__global__ void k_quant(float* __restrict__ out) {
    size_t i = (size_t)blockIdx.x * 256 + threadIdx.x;
    if (i >= (size_t)NN * OUT_CH / 4) return;
    float scale = __uint_as_float(g_qmax) / 127.f + 1e-12f;
    float4 v = ((float4*)out)[i];
    v.x = fminf(fmaxf(rintf(__fdiv_rn(v.x, scale)), -128.f), 127.f) * scale;
    v.y = fminf(fmaxf(rintf(__fdiv_rn(v.y, scale)), -128.f), 127.f) * scale;
    v.z = fminf(fmaxf(rintf(__fdiv_rn(v.z, scale)), -128.f), 127.f) * scale;
    v.w = fminf(fmaxf(rintf(__fdiv_rn(v.w, scale)), -128.f), 127.f) * scale;
    ((float4*)out)[i] = v;
}

// ---------------- launch ----------------
// k_gemm stays at launch index 3 => ncu window profiles it
extern "C" void kernel_launch(void* const* d_in, const int* in_sizes, int n_in,
                              void* d_out, int out_size) {
    const float* x        = (const float*)d_in[0];
    const void*  ei       = d_in[1];
    const float* eattr    = (const float*)d_in[2];
    const float* wlin     = (const float*)d_in[3];
    const float* wedge    = (const float*)d_in[4];
    const float* att_src  = (const float*)d_in[5];
    const float* att_dst  = (const float*)d_in[6];
    const float* att_edge = (const float*)d_in[7];
    const float* bias     = (const float*)d_in[8];
    float* out = (float*)d_out;

    cudaFuncSetAttribute(k_gemm, cudaFuncAttributeMaxDynamicSharedMemorySize, SM_TOT);

    int nscanblk = (NN + SCB - 1) / SCB;  // 196

    k_initdetect<<<(NN + 255) / 256, 256>>>((const unsigned*)ei);
    k_prep<<<1, 1024>>>(wlin, wedge, att_edge);
    k_count<<<(NE + 255) / 256, 256>>>(ei);
    k_gemm<<<(NN + BM - 1) / BM, 256, SM_TOT>>>(x, att_src, att_dst);
    k_scan1<<<nscanblk, SCB>>>();
    k_scan2<<<1, 256>>>(nscanblk);
    k_scan3<<<(NN + 256) / 256, 256>>>();
    k_edgeA<<<(NE * 8 + 255) / 256, 256>>>(ei, eattr);
    k_aggregate<<<(NN * 32 + 255) / 256, 256>>>(out, bias);
    k_quant<<<(NN * OUT_CH / 4 + 255) / 256, 256>>>(out);
}